// round 16
// baseline (speedup 1.0000x reference)
#include <cuda_runtime.h>
#include <cuda_fp16.h>
#include <cstdint>
#include <math.h>

// Problem dims
#define BB 256
#define II 1152
#define PP 8
#define JJ 10
#define DD 16
#define JD 160   // JJ*DD

// Route tiling: 4 warps/CTA; warp = 32 i as 2 TMA tiles of 16 i  (r14 winner)
#define TW 16
#define ROWB 320              // bytes per i row (160 halves)
#define TILEB (TW * ROWB)     // 5120 B per tile
#define NCHUNK 9              // 1152 / (4*32)

// Scratch (device globals; no runtime allocation allowed)
__device__ __half g_votes[(size_t)BB * II * JD];  // 94.4 MB fp16
__device__ float  g_s[3][BB * JD];                // s0, s1, s2 accumulators

typedef unsigned long long ull;

// ---------------------------------------------------------------------------
// f32x2 packed math (FFMA2 path — 2x fp32 FMA throughput)
// ---------------------------------------------------------------------------
__device__ __forceinline__ ull pack2(float lo, float hi) {
    ull d; asm("mov.b64 %0, {%1,%2};" : "=l"(d) : "f"(lo), "f"(hi)); return d;
}
__device__ __forceinline__ ull mul2(ull a, ull b) {
    ull d; asm("mul.rn.f32x2 %0, %1, %2;" : "=l"(d) : "l"(a), "l"(b)); return d;
}
__device__ __forceinline__ ull fma2(ull a, ull b, ull c) {
    ull d; asm("fma.rn.f32x2 %0, %1, %2, %3;" : "=l"(d) : "l"(a), "l"(b), "l"(c)); return d;
}
__device__ __forceinline__ float sum2(ull a) {
    float lo, hi; asm("mov.b64 {%0,%1}, %2;" : "=f"(lo), "=f"(hi) : "l"(a));
    return lo + hi;
}

// ---------------------------------------------------------------------------
// mbarrier + bulk-async helpers
// ---------------------------------------------------------------------------
__device__ __forceinline__ void mbar_init(uint32_t mbar, uint32_t cnt) {
    asm volatile("mbarrier.init.shared.b64 [%0], %1;" :: "r"(mbar), "r"(cnt) : "memory");
}
__device__ __forceinline__ void mbar_expect_tx(uint32_t mbar, uint32_t bytes) {
    asm volatile("mbarrier.arrive.expect_tx.shared.b64 _, [%0], %1;"
                 :: "r"(mbar), "r"(bytes) : "memory");
}
__device__ __forceinline__ void mbar_wait(uint32_t mbar, uint32_t parity) {
    uint32_t done;
    asm volatile(
        "{\n\t.reg .pred p;\n\t"
        "mbarrier.try_wait.parity.acquire.cta.shared::cta.b64 p, [%1], %2;\n\t"
        "selp.b32 %0, 1, 0, p;\n\t}"
        : "=r"(done) : "r"(mbar), "r"(parity) : "memory");
    if (!done) {
        asm volatile(
            "{\n\t.reg .pred P1;\n\t"
            "WAIT_LOOP_%=:\n\t"
            "mbarrier.try_wait.parity.acquire.cta.shared::cta.b64 P1, [%0], %1, 0x989680;\n\t"
            "@P1 bra.uni WAIT_DONE_%=;\n\t"
            "bra.uni WAIT_LOOP_%=;\n\t"
            "WAIT_DONE_%=:\n\t}"
            :: "r"(mbar), "r"(parity) : "memory");
    }
}
__device__ __forceinline__ void bulk_g2s(uint32_t sdst, const void* gsrc,
                                         uint32_t bytes, uint32_t mbar) {
    asm volatile(
        "cp.async.bulk.shared::cluster.global.mbarrier::complete_tx::bytes "
        "[%0], [%1], %2, [%3];"
        :: "r"(sdst), "l"(gsrc), "r"(bytes), "r"(mbar) : "memory");
}

// ---------------------------------------------------------------------------
__global__ void zero_kernel() {
    int t = blockIdx.x * blockDim.x + threadIdx.x;
    if (t < 3 * BB * JD) ((float*)g_s)[t] = 0.0f;
}

// ---------------------------------------------------------------------------
// votes[b,i,jd] = sum_p W[i,jd,p] * x[b,i,p], fp16, f32x2 packed math.
// Lane < 20 owns jd = 8*lane .. 8*lane+7 (contiguous) -> ONE STG.128 per
// batch per lane instead of five STG.b16 (5x fewer store instructions,
// 2x less LSU issue). Barrier-free: warp = one i, loops 32 batches.
// Grid (144, 8): x = i-block of 8, y = 32-batch slice.
// ---------------------------------------------------------------------------
__global__ __launch_bounds__(256) void votes_kernel(const float* __restrict__ x,
                                                    const float* __restrict__ W) {
    int wid  = threadIdx.x >> 5;
    int lane = threadIdx.x & 31;
    int i    = blockIdx.x * 8 + wid;
    int b0   = blockIdx.y * 32;
    bool act = (lane < 20);

    const float4* Wp = (const float4*)(W + (size_t)i * (JD * PP));
    ull wreg[8][4];
    if (act) {
#pragma unroll
        for (int r = 0; r < 8; r++) {
            int jd = lane * 8 + r;
            float4 w0 = Wp[jd * 2 + 0];
            float4 w1 = Wp[jd * 2 + 1];
            wreg[r][0] = pack2(w0.x, w0.y);
            wreg[r][1] = pack2(w0.z, w0.w);
            wreg[r][2] = pack2(w1.x, w1.y);
            wreg[r][3] = pack2(w1.z, w1.w);
        }
    }

    float4 xb0[2], xb1[2];
#pragma unroll
    for (int q = 0; q < 2; q++) {
        const float4* xp = (const float4*)(x + ((size_t)(b0 + q) * II + i) * PP);
        xb0[q] = __ldg(xp + 0);
        xb1[q] = __ldg(xp + 1);
    }

    for (int bi = 0; bi < 32; bi++) {
        float4 x0 = xb0[bi & 1], x1 = xb1[bi & 1];
        if (bi < 30) {
            const float4* nxp = (const float4*)(x + ((size_t)(b0 + bi + 2) * II + i) * PP);
            xb0[bi & 1] = __ldg(nxp + 0);
            xb1[bi & 1] = __ldg(nxp + 1);
        }
        if (act) {
            ull xA = pack2(x0.x, x0.y), xB = pack2(x0.z, x0.w);
            ull xC = pack2(x1.x, x1.y), xD = pack2(x1.z, x1.w);

            float res[8];
#pragma unroll
            for (int r = 0; r < 8; r++) {
                ull acc = mul2(wreg[r][3], xD);
                acc = fma2(wreg[r][2], xC, acc);
                acc = fma2(wreg[r][1], xB, acc);
                acc = fma2(wreg[r][0], xA, acc);
                res[r] = sum2(acc);
            }
            __half2 h0 = __floats2half2_rn(res[0], res[1]);
            __half2 h1 = __floats2half2_rn(res[2], res[3]);
            __half2 h2 = __floats2half2_rn(res[4], res[5]);
            __half2 h3 = __floats2half2_rn(res[6], res[7]);
            uint4 val = make_uint4(*(uint32_t*)&h0, *(uint32_t*)&h1,
                                   *(uint32_t*)&h2, *(uint32_t*)&h3);
            uint4* vout = (uint4*)(g_votes + ((size_t)(b0 + bi) * II + i) * JD);
            vout[lane] = val;
        }
    }
}

// ---------------------------------------------------------------------------
// s0[b,jd] = 0.1 * sum_i votes[b,i,jd] (softmax of zeros -> c = 1/10).
// Grid (256, 4): x = batch, y = i-quarter. Thread = half2 column pair.
// ---------------------------------------------------------------------------
__global__ __launch_bounds__(128) void s0_kernel() {
    int b  = blockIdx.x;
    int iq = blockIdx.y;
    int p  = threadIdx.x;
    if (p >= 80) return;

    const __half2* base =
        (const __half2*)g_votes + ((size_t)b * II + iq * 288) * 80 + p;
    float sx = 0.0f, sy = 0.0f;
#pragma unroll 8
    for (int i = 0; i < 288; i++) {
        float2 f = __half22float2(base[(size_t)i * 80]);
        sx += f.x; sy += f.y;
    }
    atomicAdd(&g_s[0][b * JD + 2 * p + 0], 0.1f * sx);
    atomicAdd(&g_s[0][b * JD + 2 * p + 1], 0.1f * sy);
}

// ---------------------------------------------------------------------------
// Routing pass MODE (1|2): logits = votes.(v0[+v1]) since b0 = 0.
// Grid (9, 256), 128 threads = 4 warps; warp owns 32 i as two TMA tiles
// (cp.async.bulk, warp-private mbarriers, both issued up front).
// Pass A: lane = (il = lane>>1, jh = lane&1) — 2-way-conflict LDS.128
// phases; softmax partner = lane^1. Pass B: lane owns half2 pairs
// {lane, lane+32, lane+64<16}; accumulates across both tiles.
// ---------------------------------------------------------------------------
template <int MODE>
__global__ __launch_bounds__(128) void route_kernel() {
    __shared__ __align__(16) char v_sm[4][2][TILEB];     // 40960 B
    __shared__ float c_sm[4][TW * JJ];                   // 2560 B
    __shared__ __align__(16) float vp_s[JD];             // 640 B
    __shared__ __align__(8) ull mbar[4][2];

    int b    = blockIdx.y;
    int chnk = blockIdx.x;
    int tid  = threadIdx.x;
    int w    = tid >> 5;
    int lane = tid & 31;

    // ---- warp-private TMA: init mbarriers + issue both tiles ----
    const char* gsrc = (const char*)(g_votes + ((size_t)b * II + chnk * 128 + w * 32) * JD);
    uint32_t mb0 = (uint32_t)__cvta_generic_to_shared(&mbar[w][0]);
    uint32_t mb1 = (uint32_t)__cvta_generic_to_shared(&mbar[w][1]);
    uint32_t sd0 = (uint32_t)__cvta_generic_to_shared(&v_sm[w][0][0]);
    uint32_t sd1 = (uint32_t)__cvta_generic_to_shared(&v_sm[w][1][0]);
    if (lane == 0) {
        mbar_init(mb0, 1);
        mbar_init(mb1, 1);
        asm volatile("fence.proxy.async.shared::cta;" ::: "memory");
        mbar_expect_tx(mb0, TILEB);
        bulk_g2s(sd0, gsrc, TILEB, mb0);
        mbar_expect_tx(mb1, TILEB);
        bulk_g2s(sd1, gsrc + TILEB, TILEB, mb1);
    }

    // ---- vp = squash(s0) [+ squash(s1)] : warp 0, lane j (overlaps TMA) ----
    if (tid < 32 && lane < JJ) {
        const float4* s0p = (const float4*)(&g_s[0][b * JD + lane * DD]);
        float4 a0 = s0p[0], a1 = s0p[1], a2 = s0p[2], a3 = s0p[3];
        float nn = a0.x*a0.x + a0.y*a0.y + a0.z*a0.z + a0.w*a0.w
                 + a1.x*a1.x + a1.y*a1.y + a1.z*a1.z + a1.w*a1.w
                 + a2.x*a2.x + a2.y*a2.y + a2.z*a2.z + a2.w*a2.w
                 + a3.x*a3.x + a3.y*a3.y + a3.z*a3.z + a3.w*a3.w;
        float sc = nn / (1.0f + nn) / sqrtf(nn + 1e-7f);
        float vp[DD];
        vp[0]=a0.x*sc; vp[1]=a0.y*sc; vp[2]=a0.z*sc; vp[3]=a0.w*sc;
        vp[4]=a1.x*sc; vp[5]=a1.y*sc; vp[6]=a1.z*sc; vp[7]=a1.w*sc;
        vp[8]=a2.x*sc; vp[9]=a2.y*sc; vp[10]=a2.z*sc; vp[11]=a2.w*sc;
        vp[12]=a3.x*sc; vp[13]=a3.y*sc; vp[14]=a3.z*sc; vp[15]=a3.w*sc;
        if (MODE == 2) {
            const float4* s1p = (const float4*)(&g_s[1][b * JD + lane * DD]);
            float4 c0 = s1p[0], c1 = s1p[1], c2 = s1p[2], c3 = s1p[3];
            float n1 = c0.x*c0.x + c0.y*c0.y + c0.z*c0.z + c0.w*c0.w
                     + c1.x*c1.x + c1.y*c1.y + c1.z*c1.z + c1.w*c1.w
                     + c2.x*c2.x + c2.y*c2.y + c2.z*c2.z + c2.w*c2.w
                     + c3.x*c3.x + c3.y*c3.y + c3.z*c3.z + c3.w*c3.w;
            float s1c = n1 / (1.0f + n1) / sqrtf(n1 + 1e-7f);
            vp[0]+=c0.x*s1c; vp[1]+=c0.y*s1c; vp[2]+=c0.z*s1c; vp[3]+=c0.w*s1c;
            vp[4]+=c1.x*s1c; vp[5]+=c1.y*s1c; vp[6]+=c1.z*s1c; vp[7]+=c1.w*s1c;
            vp[8]+=c2.x*s1c; vp[9]+=c2.y*s1c; vp[10]+=c2.z*s1c; vp[11]+=c2.w*s1c;
            vp[12]+=c3.x*s1c; vp[13]+=c3.y*s1c; vp[14]+=c3.z*s1c; vp[15]+=c3.w*s1c;
        }
#pragma unroll
        for (int d = 0; d < DD; d++) vp_s[lane * DD + d] = vp[d];
    }
    __syncthreads();

    int il = lane >> 1;
    int jh = lane & 1;
    int jA = lane >> 3, jB = 4 + (lane >> 3), jC = 8 + (lane >> 3);
    float2 a0 = {0.f, 0.f}, a1 = {0.f, 0.f}, a2 = {0.f, 0.f};

#pragma unroll
    for (int t = 0; t < 2; t++) {
        mbar_wait(t == 0 ? mb0 : mb1, 0);

        // ---- pass A: dots + split softmax from smem tile ----
        const char* tile = &v_sm[w][t][0];
        const uint4* vrow = (const uint4*)(tile + il * ROWB + jh * 160);
        float dots[5];
#pragma unroll
        for (int jj = 0; jj < 5; jj++) {
            int j = jh * 5 + jj;
            uint4 q0 = vrow[jj * 2 + 0];
            uint4 q1 = vrow[jj * 2 + 1];
            const __half2* h0 = (const __half2*)&q0;
            const __half2* h1 = (const __half2*)&q1;
            const float4* vpf = (const float4*)(vp_s + j * DD);
            float4 p0 = vpf[0], p1 = vpf[1], p2 = vpf[2], p3 = vpf[3];
            float dot = 0.0f;
            float2 f;
            f = __half22float2(h0[0]); dot = fmaf(f.x, p0.x, fmaf(f.y, p0.y, dot));
            f = __half22float2(h0[1]); dot = fmaf(f.x, p0.z, fmaf(f.y, p0.w, dot));
            f = __half22float2(h0[2]); dot = fmaf(f.x, p1.x, fmaf(f.y, p1.y, dot));
            f = __half22float2(h0[3]); dot = fmaf(f.x, p1.z, fmaf(f.y, p1.w, dot));
            f = __half22float2(h1[0]); dot = fmaf(f.x, p2.x, fmaf(f.y, p2.y, dot));
            f = __half22float2(h1[1]); dot = fmaf(f.x, p2.z, fmaf(f.y, p2.w, dot));
            f = __half22float2(h1[2]); dot = fmaf(f.x, p3.x, fmaf(f.y, p3.y, dot));
            f = __half22float2(h1[3]); dot = fmaf(f.x, p3.z, fmaf(f.y, p3.w, dot));
            dots[jj] = dot;
        }
        float m5 = dots[0];
#pragma unroll
        for (int jj = 1; jj < 5; jj++) m5 = fmaxf(m5, dots[jj]);
        float m = fmaxf(m5, __shfl_xor_sync(0xffffffffu, m5, 1));
        float e[5], s5 = 0.0f;
#pragma unroll
        for (int jj = 0; jj < 5; jj++) { e[jj] = __expf(dots[jj] - m); s5 += e[jj]; }
        float Z = s5 + __shfl_xor_sync(0xffffffffu, s5, 1);
        float rinv = 1.0f / Z;
#pragma unroll
        for (int jj = 0; jj < 5; jj++)
            c_sm[w][il * JJ + jh * 5 + jj] = e[jj] * rinv;
        __syncwarp();

        // ---- pass B: lane owns half2 pairs {lane, lane+32, lane+64(<16)} ----
        const __half2* vb2 = (const __half2*)tile;   // row stride 80 half2
        const float*   cb  = &c_sm[w][0];
#pragma unroll 4
        for (int i = 0; i < TW; i++) {
            const float* cr = cb + i * JJ;
            float2 f0 = __half22float2(vb2[i * 80 + lane]);
            float c0 = cr[jA];
            a0.x = fmaf(c0, f0.x, a0.x); a0.y = fmaf(c0, f0.y, a0.y);
            float2 f1 = __half22float2(vb2[i * 80 + lane + 32]);
            float c1 = cr[jB];
            a1.x = fmaf(c1, f1.x, a1.x); a1.y = fmaf(c1, f1.y, a1.y);
            if (lane < 16) {
                float2 f2 = __half22float2(vb2[i * 80 + lane + 64]);
                float c2 = cr[jC];
                a2.x = fmaf(c2, f2.x, a2.x); a2.y = fmaf(c2, f2.y, a2.y);
            }
        }
        __syncwarp();
    }

    float* sdst = &g_s[MODE][b * JD];
    atomicAdd(sdst + 2 * lane + 0,   a0.x);
    atomicAdd(sdst + 2 * lane + 1,   a0.y);
    atomicAdd(sdst + 2 * lane + 64,  a1.x);
    atomicAdd(sdst + 2 * lane + 65,  a1.y);
    if (lane < 16) {
        atomicAdd(sdst + 2 * lane + 128, a2.x);
        atomicAdd(sdst + 2 * lane + 129, a2.y);
    }
}

// ---------------------------------------------------------------------------
__global__ void squash_kernel(const float* __restrict__ s, float* __restrict__ out) {
    int t = blockIdx.x * blockDim.x + threadIdx.x;
    if (t >= BB * JJ) return;
    const float* sp = s + t * DD;
    float v[DD];
    float s2 = 0.0f;
#pragma unroll
    for (int d = 0; d < DD; d++) { v[d] = sp[d]; s2 = fmaf(v[d], v[d], s2); }
    float scale = s2 / (1.0f + s2) / sqrtf(s2 + 1e-7f);
#pragma unroll
    for (int d = 0; d < DD; d++) out[t * DD + d] = v[d] * scale;
}

// ---------------------------------------------------------------------------
extern "C" void kernel_launch(void* const* d_in, const int* in_sizes, int n_in,
                              void* d_out, int out_size) {
    const float* x = (const float*)d_in[0];   // [256,1152,8]
    const float* W = (const float*)d_in[1];   // [1152,10,16,8]
    float* out = (float*)d_out;               // [256,10,16]

    float* gs = nullptr;
    cudaGetSymbolAddress((void**)&gs, g_s);

    zero_kernel<<<(3 * BB * JD + 255) / 256, 256>>>();
    votes_kernel<<<dim3(II / 8, 8), 256>>>(x, W);
    s0_kernel<<<dim3(BB, 4), 128>>>();

    route_kernel<1><<<dim3(NCHUNK, BB), 128>>>();
    route_kernel<2><<<dim3(NCHUNK, BB), 128>>>();

    squash_kernel<<<(BB * JJ + 255) / 256, 256>>>(gs + 2 * BB * JD, out);
}

// round 17
// speedup vs baseline: 1.3662x; 1.3662x over previous
#include <cuda_runtime.h>
#include <cuda_fp16.h>
#include <cstdint>
#include <math.h>

// Problem dims
#define BB 256
#define II 1152
#define PP 8
#define JJ 10
#define DD 16
#define JD 160   // JJ*DD

// Route tiling: 4 warps/CTA; warp = 32 i as 2 TMA tiles of 16 i  (r14 winner)
#define TW 16
#define ROWB 320              // bytes per i row (160 halves)
#define TILEB (TW * ROWB)     // 5120 B per tile
#define NCHUNK 9              // 1152 / (4*32)

// Scratch (device globals; no runtime allocation allowed)
__device__ __half g_votes[(size_t)BB * II * JD];  // 94.4 MB fp16
__device__ float  g_s[3][BB * JD];                // s0, s1, s2 accumulators

typedef unsigned long long ull;

// ---------------------------------------------------------------------------
// f32x2 packed math (FFMA2 path — 2x fp32 FMA throughput)
// ---------------------------------------------------------------------------
__device__ __forceinline__ ull pack2(float lo, float hi) {
    ull d; asm("mov.b64 %0, {%1,%2};" : "=l"(d) : "f"(lo), "f"(hi)); return d;
}
__device__ __forceinline__ ull mul2(ull a, ull b) {
    ull d; asm("mul.rn.f32x2 %0, %1, %2;" : "=l"(d) : "l"(a), "l"(b)); return d;
}
__device__ __forceinline__ ull fma2(ull a, ull b, ull c) {
    ull d; asm("fma.rn.f32x2 %0, %1, %2, %3;" : "=l"(d) : "l"(a), "l"(b), "l"(c)); return d;
}
__device__ __forceinline__ float sum2(ull a) {
    float lo, hi; asm("mov.b64 {%0,%1}, %2;" : "=f"(lo), "=f"(hi) : "l"(a));
    return lo + hi;
}

// ---------------------------------------------------------------------------
// mbarrier + bulk-async helpers
// ---------------------------------------------------------------------------
__device__ __forceinline__ void mbar_init(uint32_t mbar, uint32_t cnt) {
    asm volatile("mbarrier.init.shared.b64 [%0], %1;" :: "r"(mbar), "r"(cnt) : "memory");
}
__device__ __forceinline__ void mbar_expect_tx(uint32_t mbar, uint32_t bytes) {
    asm volatile("mbarrier.arrive.expect_tx.shared.b64 _, [%0], %1;"
                 :: "r"(mbar), "r"(bytes) : "memory");
}
__device__ __forceinline__ void mbar_wait(uint32_t mbar, uint32_t parity) {
    uint32_t done;
    asm volatile(
        "{\n\t.reg .pred p;\n\t"
        "mbarrier.try_wait.parity.acquire.cta.shared::cta.b64 p, [%1], %2;\n\t"
        "selp.b32 %0, 1, 0, p;\n\t}"
        : "=r"(done) : "r"(mbar), "r"(parity) : "memory");
    if (!done) {
        asm volatile(
            "{\n\t.reg .pred P1;\n\t"
            "WAIT_LOOP_%=:\n\t"
            "mbarrier.try_wait.parity.acquire.cta.shared::cta.b64 P1, [%0], %1, 0x989680;\n\t"
            "@P1 bra.uni WAIT_DONE_%=;\n\t"
            "bra.uni WAIT_LOOP_%=;\n\t"
            "WAIT_DONE_%=:\n\t}"
            :: "r"(mbar), "r"(parity) : "memory");
    }
}
__device__ __forceinline__ void bulk_g2s(uint32_t sdst, const void* gsrc,
                                         uint32_t bytes, uint32_t mbar) {
    asm volatile(
        "cp.async.bulk.shared::cluster.global.mbarrier::complete_tx::bytes "
        "[%0], [%1], %2, [%3];"
        :: "r"(sdst), "l"(gsrc), "r"(bytes), "r"(mbar) : "memory");
}
__device__ __forceinline__ void bulk_s2g(void* gdst, uint32_t ssrc, uint32_t bytes) {
    asm volatile(
        "cp.async.bulk.global.shared::cta.bulk_group [%0], [%1], %2;"
        :: "l"(gdst), "r"(ssrc), "r"(bytes) : "memory");
}
__device__ __forceinline__ void bulk_commit() {
    asm volatile("cp.async.bulk.commit_group;" ::: "memory");
}
template <int N>
__device__ __forceinline__ void bulk_wait() {
    asm volatile("cp.async.bulk.wait_group %0;" :: "n"(N) : "memory");
}

// ---------------------------------------------------------------------------
__global__ void zero_kernel() {
    int t = blockIdx.x * blockDim.x + threadIdx.x;
    if (t < 3 * BB * JD) ((float*)g_s)[t] = 0.0f;
}

// ---------------------------------------------------------------------------
// votes[b,i,jd] = sum_p W[i,jd,p] * x[b,i,p], fp16, f32x2 packed math.
// r12 lane structure (warp = one i, lane owns jd = lane+32k, all lanes hot),
// but global stores via TMA: warps STS into a double-buffered smem stage,
// thread0 issues ONE 2560B cp.async.bulk store per batch (CTA output is
// contiguous: votes[b, i0..i0+7, :]). LSU handles only cheap STS.
// Grid (144, 8): x = i-block of 8, y = 32-batch slice.
// ---------------------------------------------------------------------------
__global__ __launch_bounds__(256) void votes_kernel(const float* __restrict__ x,
                                                    const float* __restrict__ W) {
    __shared__ __align__(16) __half stage[2][8][JD];   // 2 x 2560 B

    int tid  = threadIdx.x;
    int wid  = tid >> 5;
    int lane = tid & 31;
    int i0   = blockIdx.x * 8;
    int i    = i0 + wid;
    int b0   = blockIdx.y * 32;

    const float4* Wp = (const float4*)(W + (size_t)i * (JD * PP));
    ull wreg[5][4];
#pragma unroll
    for (int k = 0; k < 5; k++) {
        int jd = lane + 32 * k;
        float4 w0 = Wp[jd * 2 + 0];
        float4 w1 = Wp[jd * 2 + 1];
        wreg[k][0] = pack2(w0.x, w0.y);
        wreg[k][1] = pack2(w0.z, w0.w);
        wreg[k][2] = pack2(w1.x, w1.y);
        wreg[k][3] = pack2(w1.z, w1.w);
    }

    float4 xb0[2], xb1[2];
#pragma unroll
    for (int q = 0; q < 2; q++) {
        const float4* xp = (const float4*)(x + ((size_t)(b0 + q) * II + i) * PP);
        xb0[q] = __ldg(xp + 0);
        xb1[q] = __ldg(xp + 1);
    }

    for (int bi = 0; bi < 32; bi++) {
        float4 x0 = xb0[bi & 1], x1 = xb1[bi & 1];
        if (bi < 30) {
            const float4* nxp = (const float4*)(x + ((size_t)(b0 + bi + 2) * II + i) * PP);
            xb0[bi & 1] = __ldg(nxp + 0);
            xb1[bi & 1] = __ldg(nxp + 1);
        }
        ull xA = pack2(x0.x, x0.y), xB = pack2(x0.z, x0.w);
        ull xC = pack2(x1.x, x1.y), xD = pack2(x1.z, x1.w);

        __half* srow = &stage[bi & 1][wid][0];
#pragma unroll
        for (int k = 0; k < 5; k++) {
            ull acc = mul2(wreg[k][3], xD);
            acc = fma2(wreg[k][2], xC, acc);
            acc = fma2(wreg[k][1], xB, acc);
            acc = fma2(wreg[k][0], xA, acc);
            srow[lane + 32 * k] = __float2half_rn(sum2(acc));
        }
        __syncthreads();
        if (tid == 0) {
            asm volatile("fence.proxy.async.shared::cta;" ::: "memory");
            uint32_t ssrc = (uint32_t)__cvta_generic_to_shared(&stage[bi & 1][0][0]);
            void* gdst = (void*)(g_votes + ((size_t)(b0 + bi) * II + i0) * JD);
            bulk_s2g(gdst, ssrc, 8 * JD * 2);
            bulk_commit();
            bulk_wait<1>();   // the other buffer's store has retired -> reusable
        }
        __syncthreads();
    }
    if (tid == 0) bulk_wait<0>();
}

// ---------------------------------------------------------------------------
// s0[b,jd] = 0.1 * sum_i votes[b,i,jd] (softmax of zeros -> c = 1/10).
// Grid (256, 4): x = batch, y = i-quarter. Thread = half2 column pair.
// ---------------------------------------------------------------------------
__global__ __launch_bounds__(128) void s0_kernel() {
    int b  = blockIdx.x;
    int iq = blockIdx.y;
    int p  = threadIdx.x;
    if (p >= 80) return;

    const __half2* base =
        (const __half2*)g_votes + ((size_t)b * II + iq * 288) * 80 + p;
    float sx = 0.0f, sy = 0.0f;
#pragma unroll 8
    for (int i = 0; i < 288; i++) {
        float2 f = __half22float2(base[(size_t)i * 80]);
        sx += f.x; sy += f.y;
    }
    atomicAdd(&g_s[0][b * JD + 2 * p + 0], 0.1f * sx);
    atomicAdd(&g_s[0][b * JD + 2 * p + 1], 0.1f * sy);
}

// ---------------------------------------------------------------------------
// Routing pass MODE (1|2): logits = votes.(v0[+v1]) since b0 = 0.
// Grid (9, 256), 128 threads = 4 warps; warp owns 32 i as two TMA tiles
// (cp.async.bulk, warp-private mbarriers, both issued up front).
// Pass A: lane = (il = lane>>1, jh = lane&1) — 2-way-conflict LDS.128
// phases; softmax partner = lane^1. Pass B: lane owns half2 pairs
// {lane, lane+32, lane+64<16}; accumulates across both tiles.
// (Exact r14 winner.)
// ---------------------------------------------------------------------------
template <int MODE>
__global__ __launch_bounds__(128) void route_kernel() {
    __shared__ __align__(16) char v_sm[4][2][TILEB];     // 40960 B
    __shared__ float c_sm[4][TW * JJ];                   // 2560 B
    __shared__ __align__(16) float vp_s[JD];             // 640 B
    __shared__ __align__(8) ull mbar[4][2];

    int b    = blockIdx.y;
    int chnk = blockIdx.x;
    int tid  = threadIdx.x;
    int w    = tid >> 5;
    int lane = tid & 31;

    // ---- warp-private TMA: init mbarriers + issue both tiles ----
    const char* gsrc = (const char*)(g_votes + ((size_t)b * II + chnk * 128 + w * 32) * JD);
    uint32_t mb0 = (uint32_t)__cvta_generic_to_shared(&mbar[w][0]);
    uint32_t mb1 = (uint32_t)__cvta_generic_to_shared(&mbar[w][1]);
    uint32_t sd0 = (uint32_t)__cvta_generic_to_shared(&v_sm[w][0][0]);
    uint32_t sd1 = (uint32_t)__cvta_generic_to_shared(&v_sm[w][1][0]);
    if (lane == 0) {
        mbar_init(mb0, 1);
        mbar_init(mb1, 1);
        asm volatile("fence.proxy.async.shared::cta;" ::: "memory");
        mbar_expect_tx(mb0, TILEB);
        bulk_g2s(sd0, gsrc, TILEB, mb0);
        mbar_expect_tx(mb1, TILEB);
        bulk_g2s(sd1, gsrc + TILEB, TILEB, mb1);
    }

    // ---- vp = squash(s0) [+ squash(s1)] : warp 0, lane j (overlaps TMA) ----
    if (tid < 32 && lane < JJ) {
        const float4* s0p = (const float4*)(&g_s[0][b * JD + lane * DD]);
        float4 a0 = s0p[0], a1 = s0p[1], a2 = s0p[2], a3 = s0p[3];
        float nn = a0.x*a0.x + a0.y*a0.y + a0.z*a0.z + a0.w*a0.w
                 + a1.x*a1.x + a1.y*a1.y + a1.z*a1.z + a1.w*a1.w
                 + a2.x*a2.x + a2.y*a2.y + a2.z*a2.z + a2.w*a2.w
                 + a3.x*a3.x + a3.y*a3.y + a3.z*a3.z + a3.w*a3.w;
        float sc = nn / (1.0f + nn) / sqrtf(nn + 1e-7f);
        float vp[DD];
        vp[0]=a0.x*sc; vp[1]=a0.y*sc; vp[2]=a0.z*sc; vp[3]=a0.w*sc;
        vp[4]=a1.x*sc; vp[5]=a1.y*sc; vp[6]=a1.z*sc; vp[7]=a1.w*sc;
        vp[8]=a2.x*sc; vp[9]=a2.y*sc; vp[10]=a2.z*sc; vp[11]=a2.w*sc;
        vp[12]=a3.x*sc; vp[13]=a3.y*sc; vp[14]=a3.z*sc; vp[15]=a3.w*sc;
        if (MODE == 2) {
            const float4* s1p = (const float4*)(&g_s[1][b * JD + lane * DD]);
            float4 c0 = s1p[0], c1 = s1p[1], c2 = s1p[2], c3 = s1p[3];
            float n1 = c0.x*c0.x + c0.y*c0.y + c0.z*c0.z + c0.w*c0.w
                     + c1.x*c1.x + c1.y*c1.y + c1.z*c1.z + c1.w*c1.w
                     + c2.x*c2.x + c2.y*c2.y + c2.z*c2.z + c2.w*c2.w
                     + c3.x*c3.x + c3.y*c3.y + c3.z*c3.z + c3.w*c3.w;
            float s1c = n1 / (1.0f + n1) / sqrtf(n1 + 1e-7f);
            vp[0]+=c0.x*s1c; vp[1]+=c0.y*s1c; vp[2]+=c0.z*s1c; vp[3]+=c0.w*s1c;
            vp[4]+=c1.x*s1c; vp[5]+=c1.y*s1c; vp[6]+=c1.z*s1c; vp[7]+=c1.w*s1c;
            vp[8]+=c2.x*s1c; vp[9]+=c2.y*s1c; vp[10]+=c2.z*s1c; vp[11]+=c2.w*s1c;
            vp[12]+=c3.x*s1c; vp[13]+=c3.y*s1c; vp[14]+=c3.z*s1c; vp[15]+=c3.w*s1c;
        }
#pragma unroll
        for (int d = 0; d < DD; d++) vp_s[lane * DD + d] = vp[d];
    }
    __syncthreads();

    int il = lane >> 1;
    int jh = lane & 1;
    int jA = lane >> 3, jB = 4 + (lane >> 3), jC = 8 + (lane >> 3);
    float2 a0 = {0.f, 0.f}, a1 = {0.f, 0.f}, a2 = {0.f, 0.f};

#pragma unroll
    for (int t = 0; t < 2; t++) {
        mbar_wait(t == 0 ? mb0 : mb1, 0);

        // ---- pass A: dots + split softmax from smem tile ----
        const char* tile = &v_sm[w][t][0];
        const uint4* vrow = (const uint4*)(tile + il * ROWB + jh * 160);
        float dots[5];
#pragma unroll
        for (int jj = 0; jj < 5; jj++) {
            int j = jh * 5 + jj;
            uint4 q0 = vrow[jj * 2 + 0];
            uint4 q1 = vrow[jj * 2 + 1];
            const __half2* h0 = (const __half2*)&q0;
            const __half2* h1 = (const __half2*)&q1;
            const float4* vpf = (const float4*)(vp_s + j * DD);
            float4 p0 = vpf[0], p1 = vpf[1], p2 = vpf[2], p3 = vpf[3];
            float dot = 0.0f;
            float2 f;
            f = __half22float2(h0[0]); dot = fmaf(f.x, p0.x, fmaf(f.y, p0.y, dot));
            f = __half22float2(h0[1]); dot = fmaf(f.x, p0.z, fmaf(f.y, p0.w, dot));
            f = __half22float2(h0[2]); dot = fmaf(f.x, p1.x, fmaf(f.y, p1.y, dot));
            f = __half22float2(h0[3]); dot = fmaf(f.x, p1.z, fmaf(f.y, p1.w, dot));
            f = __half22float2(h1[0]); dot = fmaf(f.x, p2.x, fmaf(f.y, p2.y, dot));
            f = __half22float2(h1[1]); dot = fmaf(f.x, p2.z, fmaf(f.y, p2.w, dot));
            f = __half22float2(h1[2]); dot = fmaf(f.x, p3.x, fmaf(f.y, p3.y, dot));
            f = __half22float2(h1[3]); dot = fmaf(f.x, p3.z, fmaf(f.y, p3.w, dot));
            dots[jj] = dot;
        }
        float m5 = dots[0];
#pragma unroll
        for (int jj = 1; jj < 5; jj++) m5 = fmaxf(m5, dots[jj]);
        float m = fmaxf(m5, __shfl_xor_sync(0xffffffffu, m5, 1));
        float e[5], s5 = 0.0f;
#pragma unroll
        for (int jj = 0; jj < 5; jj++) { e[jj] = __expf(dots[jj] - m); s5 += e[jj]; }
        float Z = s5 + __shfl_xor_sync(0xffffffffu, s5, 1);
        float rinv = 1.0f / Z;
#pragma unroll
        for (int jj = 0; jj < 5; jj++)
            c_sm[w][il * JJ + jh * 5 + jj] = e[jj] * rinv;
        __syncwarp();

        // ---- pass B: lane owns half2 pairs {lane, lane+32, lane+64(<16)} ----
        const __half2* vb2 = (const __half2*)tile;   // row stride 80 half2
        const float*   cb  = &c_sm[w][0];
#pragma unroll 4
        for (int i = 0; i < TW; i++) {
            const float* cr = cb + i * JJ;
            float2 f0 = __half22float2(vb2[i * 80 + lane]);
            float c0 = cr[jA];
            a0.x = fmaf(c0, f0.x, a0.x); a0.y = fmaf(c0, f0.y, a0.y);
            float2 f1 = __half22float2(vb2[i * 80 + lane + 32]);
            float c1 = cr[jB];
            a1.x = fmaf(c1, f1.x, a1.x); a1.y = fmaf(c1, f1.y, a1.y);
            if (lane < 16) {
                float2 f2 = __half22float2(vb2[i * 80 + lane + 64]);
                float c2 = cr[jC];
                a2.x = fmaf(c2, f2.x, a2.x); a2.y = fmaf(c2, f2.y, a2.y);
            }
        }
        __syncwarp();
    }

    float* sdst = &g_s[MODE][b * JD];
    atomicAdd(sdst + 2 * lane + 0,   a0.x);
    atomicAdd(sdst + 2 * lane + 1,   a0.y);
    atomicAdd(sdst + 2 * lane + 64,  a1.x);
    atomicAdd(sdst + 2 * lane + 65,  a1.y);
    if (lane < 16) {
        atomicAdd(sdst + 2 * lane + 128, a2.x);
        atomicAdd(sdst + 2 * lane + 129, a2.y);
    }
}

// ---------------------------------------------------------------------------
__global__ void squash_kernel(const float* __restrict__ s, float* __restrict__ out) {
    int t = blockIdx.x * blockDim.x + threadIdx.x;
    if (t >= BB * JJ) return;
    const float* sp = s + t * DD;
    float v[DD];
    float s2 = 0.0f;
#pragma unroll
    for (int d = 0; d < DD; d++) { v[d] = sp[d]; s2 = fmaf(v[d], v[d], s2); }
    float scale = s2 / (1.0f + s2) / sqrtf(s2 + 1e-7f);
#pragma unroll
    for (int d = 0; d < DD; d++) out[t * DD + d] = v[d] * scale;
}

// ---------------------------------------------------------------------------
extern "C" void kernel_launch(void* const* d_in, const int* in_sizes, int n_in,
                              void* d_out, int out_size) {
    const float* x = (const float*)d_in[0];   // [256,1152,8]
    const float* W = (const float*)d_in[1];   // [1152,10,16,8]
    float* out = (float*)d_out;               // [256,10,16]

    float* gs = nullptr;
    cudaGetSymbolAddress((void**)&gs, g_s);

    zero_kernel<<<(3 * BB * JD + 255) / 256, 256>>>();
    votes_kernel<<<dim3(II / 8, 8), 256>>>(x, W);
    s0_kernel<<<dim3(BB, 4), 128>>>();

    route_kernel<1><<<dim3(NCHUNK, BB), 128>>>();
    route_kernel<2><<<dim3(NCHUNK, BB), 128>>>();

    squash_kernel<<<(BB * JJ + 255) / 256, 256>>>(gs + 2 * BB * JD, out);
}